// round 15
// baseline (speedup 1.0000x reference)
#include <cuda_runtime.h>
#include <cuda_bf16.h>

// 10-qubit state-vector sim, one warp/element, f32x2 packed.
// Position: bits[9:5]=lane, bits[4:1]=j, bit[0]=half.
// CNOT layer 0 folded into the initial product state. Per layer: CNOT
// remnant, merged diagonal G_l, Y layer (reg gates, lane<->reg transpose,
// reg gates). Lane gathers of layers 1/2/3 folded into adjacent transposes;
// G1,G3 stored lane-permuted. Readout in the pre-restore frame.
// Transpose: R11 float scheme (STS.32 writes / LDS.64 reads, no selects)
// with DUAL scratch buffers (vr/vi) -> 2 syncwarps per transpose and
// overlapped reads. 113.6KB smem/block, still 2 CTAs/SM.

#define NQ 10
#define BATCH 16384
#define EMB 64
#define SGN2 0x8000000080000000ULL

typedef unsigned long long ull;

__device__ float d_G4f[5 * 16 * 32 * 4];
__device__ float d_Yt[50];
__device__ float d_V0[40];

__device__ __forceinline__ ull pack2(float lo, float hi) {
    ull r; asm("mov.b64 %0, {%1,%2};" : "=l"(r) : "f"(lo), "f"(hi)); return r;
}
__device__ __forceinline__ void unpack2(ull v, float& lo, float& hi) {
    asm("mov.b64 {%0,%1}, %2;" : "=f"(lo), "=f"(hi) : "l"(v));
}
__device__ __forceinline__ ull splat2(float x) { return pack2(x, x); }
__device__ __forceinline__ ull fma2(ull a, ull b, ull c) {
    ull d; asm("fma.rn.f32x2 %0, %1, %2, %3;" : "=l"(d) : "l"(a), "l"(b), "l"(c)); return d;
}
__device__ __forceinline__ ull mul2(ull a, ull b) {
    ull d; asm("mul.rn.f32x2 %0, %1, %2;" : "=l"(d) : "l"(a), "l"(b)); return d;
}
__device__ __forceinline__ ull swap64(ull v) {
    float lo, hi; unpack2(v, lo, hi); return pack2(hi, lo);
}
__device__ __forceinline__ float shxf(float v, int m) {
    return __shfl_xor_sync(0xffffffffu, v, m);
}

// ---- prep: diagonals (lane-permuted for l=1,3) + coefficients -------------
__global__ void prep_kernel(const float* __restrict__ weights) {
    const int t = threadIdx.x;
    const int l = blockIdx.x;  // 0..4
    if (l == 0) {
        if (t < 50) {
            int ll = t / 10 + 1, w = t % 10;
            d_Yt[t] = tanf(0.5f * weights[ll * 30 + w * 3 + 1]);
        }
        if (t >= 64 && t < 74) {
            int w = t - 64;
            float phi = weights[w * 3 + 0];
            float th  = weights[w * 3 + 1];
            float sth, cth, sph, cph;
            sincosf(0.5f * th, &sth, &cth);
            sincosf(0.5f * phi, &sph, &cph);
            d_V0[w * 4] = cth; d_V0[w * 4 + 1] = sth;
            d_V0[w * 4 + 2] = cph; d_V0[w * 4 + 3] = sph;
        }
    }
    const int k = t;  // 1024 threads
    {
        const int r = l + 1;
        int m = k;
        for (int w = 9; w >= 0; w--) {
            int c = w, tt = (w + r) % 10;
            if ((m >> (9 - c)) & 1) m ^= 1 << (9 - tt);
        }
        float e = 0.f, scale = 1.f;
        for (int w = 0; w < 10; w++) {
            float phi1 = weights[(l + 1) * 30 + w * 3 + 0];
            float om0  = weights[l * 30 + w * 3 + 2];
            e += 0.5f * phi1 * (((k >> (9 - w)) & 1) ? 1.f : -1.f);
            e += 0.5f * om0  * (((m >> (9 - w)) & 1) ? 1.f : -1.f);
            scale *= cosf(0.5f * weights[(l + 1) * 30 + w * 3 + 1]);
        }
        float gi, gr; sincosf(e, &gi, &gr);
        gr *= scale; gi *= scale;
        int pos = (l & 1) ? (((k & 0x1F) << 5) | ((k >> 5) & 0x1F)) : k;
        int ln = pos >> 5;
        const int jj = (pos >> 1) & 15, hh = pos & 1;
        if (l == 1) {   // slot = F1(lane): b0^=b2, b1^=b3, b2^=b4
            int b = ln;
            ln = b ^ ((b >> 2) & 1) ^ ((((b >> 3) & 1)) << 1) ^ ((((b >> 4) & 1)) << 2);
        } else if (l == 3) {  // slot = F3(lane): b0^=b4
            ln = ln ^ ((ln >> 4) & 1);
        }
        const int b4 = ((l * 16 + jj) * 32 + ln) * 4;
        d_G4f[b4 + hh]     = gr;
        d_G4f[b4 + 2 + hh] = gi;
    }
}

// ---- tangent-form RY shear (reg domain only) ------------------------------
template <int W>
__device__ __forceinline__ void y_gate(ull* vr, ull* vi, float t) {
    constexpr int BIT = 9 - W;
    if constexpr (BIT >= 1) {
        constexpr int MJ = 1 << (BIT - 1);
        const ull T = splat2(t), NT = splat2(-t);
#pragma unroll
        for (int j = 0; j < 16; j++) {
            if (!(j & MJ)) {
                const int j1 = j | MJ;
                ull x0r = vr[j], x0i = vi[j], x1r = vr[j1], x1i = vi[j1];
                vr[j]  = fma2(NT, x1r, x0r);
                vi[j]  = fma2(NT, x1i, x0i);
                vr[j1] = fma2(T, x0r, x1r);
                vi[j1] = fma2(T, x0i, x1i);
            }
        }
    } else {
        const ull SP = pack2(-t, t);
#pragma unroll
        for (int j = 0; j < 16; j++) {
            vr[j] = fma2(SP, swap64(vr[j]), vr[j]);
            vi[j] = fma2(SP, swap64(vi[j]), vi[j]);
        }
    }
}

// ---- single CNOT (qubit template) -----------------------------------------
template <int CQ, int TQ>
__device__ __forceinline__ void cnot_p(ull* vr, ull* vi, int lane) {
    constexpr int BC = 9 - CQ, BT = 9 - TQ;
    if constexpr (BC >= 5 && BT >= 1) {
        constexpr int MCL = 1 << (BC - 5), MJ = 1 << (BT - 1);
        const bool ctrl = (lane & MCL) != 0;
#pragma unroll
        for (int j = 0; j < 16; j++) {
            if (!(j & MJ)) {
                const int j1 = j | MJ;
                ull a = vr[j], b = vr[j1];
                vr[j] = ctrl ? b : a; vr[j1] = ctrl ? a : b;
                ull p = vi[j], q = vi[j1];
                vi[j] = ctrl ? q : p; vi[j1] = ctrl ? p : q;
            }
        }
    } else if constexpr (BC >= 5) {
        constexpr int MCL = 1 << (BC - 5);
        const bool ctrl = (lane & MCL) != 0;
#pragma unroll
        for (int j = 0; j < 16; j++) {
            ull rs = swap64(vr[j]), is = swap64(vi[j]);
            vr[j] = ctrl ? rs : vr[j];
            vi[j] = ctrl ? is : vi[j];
        }
    } else if constexpr (BC >= 1 && BT >= 1) {
        constexpr int MJ = 1 << (BC - 1), MT = 1 << (BT - 1);
#pragma unroll
        for (int j = 0; j < 16; j++) {
            if ((j & MJ) && !(j & MT)) {
                const int j1 = j | MT;
                ull t;
                t = vr[j]; vr[j] = vr[j1]; vr[j1] = t;
                t = vi[j]; vi[j] = vi[j1]; vi[j1] = t;
            }
        }
    } else if constexpr (BC >= 1) {
        constexpr int MJ = 1 << (BC - 1);
#pragma unroll
        for (int j = 0; j < 16; j++) {
            if (j & MJ) { vr[j] = swap64(vr[j]); vi[j] = swap64(vi[j]); }
        }
    }
}
template <int VC, int VT>
__device__ __forceinline__ void cnot_v(ull* vr, ull* vi, int lane) {
    cnot_p<9 - VC, 9 - VT>(vr, vi, lane);
}

template <int MJ>
__device__ __forceinline__ void ctrl_regswap(ull* vr, ull* vi, bool ctrl) {
#pragma unroll
    for (int j = 0; j < 16; j++) {
        if (!(j & MJ)) {
            const int j1 = j | MJ;
            ull a = vr[j], b = vr[j1];
            vr[j] = ctrl ? b : a; vr[j1] = ctrl ? a : b;
            ull p = vi[j], q = vi[j1];
            vi[j] = ctrl ? q : p; vi[j1] = ctrl ? p : q;
        }
    }
}

// ---- Lambda0 merged pieces ------------------------------------------------
__device__ constexpr int trail_mask_ct(int R, int j, int h) {
    int m = 0;
    for (int w = 5; w <= 9; w++) {
        int t = (w + R) % 10;
        if (w + R >= 10 && t <= 4) {
            int bit = (w == 9) ? h : ((j >> (8 - w)) & 1);
            if (bit) m ^= 16 >> t;
        }
    }
    return m;
}
template <int R, int J>
__device__ __forceinline__ void cnot_trail_j(ull* vr, ull* vi) {
    if constexpr (J < 16) {
        constexpr int mlo = trail_mask_ct(R, J, 0);
        constexpr int mhi = trail_mask_ct(R, J, 1);
        if constexpr (mlo != 0 || mhi != 0) {
            float rlo, rhi, ilo, ihi;
            unpack2(vr[J], rlo, rhi);
            unpack2(vi[J], ilo, ihi);
            if constexpr (mlo != 0) { rlo = shxf(rlo, mlo); ilo = shxf(ilo, mlo); }
            if constexpr (mhi != 0) { rhi = shxf(rhi, mhi); ihi = shxf(ihi, mhi); }
            vr[J] = pack2(rlo, rhi);
            vi[J] = pack2(ilo, ihi);
        }
        cnot_trail_j<R, J + 1>(vr, vi);
    }
}
template <int L, int W, int WEND>
__device__ __forceinline__ void cnots_seq(ull* vr, ull* vi, int lane) {
    if constexpr (W <= WEND) {
        cnot_p<W, (W + L % 9 + 1) % 10>(vr, vi, lane);
        cnots_seq<L, W + 1, WEND>(vr, vi, lane);
    }
}
__device__ __forceinline__ void cnot_layer4(ull* vr, ull* vi, int lane) {
    cnots_seq<4, 0, 4>(vr, vi, lane);
    cnot_trail_j<5, 0>(vr, vi);
}

// ---- Lambda1 mask groups (layers 1, 3) ------------------------------------
template <int J>
__device__ __forceinline__ void mask_xor_L1(ull* vr, ull* vi) {
    if constexpr (J < 16) {
        constexpr int mlo = (J & 1) << 4;
        constexpr int mhi = ((J & 1) << 4) | 8;
        float rlo, rhi, ilo, ihi;
        unpack2(vr[J], rlo, rhi);
        unpack2(vi[J], ilo, ihi);
        if constexpr (mlo != 0) { rlo = shxf(rlo, mlo); ilo = shxf(ilo, mlo); }
        rhi = shxf(rhi, mhi); ihi = shxf(ihi, mhi);
        vr[J] = pack2(rlo, rhi);
        vi[J] = pack2(ilo, ihi);
        mask_xor_L1<J + 1>(vr, vi);
    }
}
template <int J>
__device__ __forceinline__ void mask_xor_L3(ull* vr, ull* vi) {
    if constexpr (J < 16) {
        constexpr int base = (((J >> 2) & 1) << 4) | (((J >> 1) & 1) << 3) | ((J & 1) << 2);
        constexpr int mlo = base;
        constexpr int mhi = base | 2;
        float rlo, rhi, ilo, ihi;
        unpack2(vr[J], rlo, rhi);
        unpack2(vi[J], ilo, ihi);
        if constexpr (mlo != 0) { rlo = shxf(rlo, mlo); ilo = shxf(ilo, mlo); }
        rhi = shxf(rhi, mhi); ihi = shxf(ihi, mhi);
        vr[J] = pack2(rlo, rhi);
        vi[J] = pack2(ilo, ihi);
        mask_xor_L3<J + 1>(vr, vi);
    }
}

// ---- CNOT layers with gathers deferred/advanced ---------------------------
__device__ __forceinline__ void cnot_layer1_def(ull* vr, ull* vi, int lane) {
    cnot_v<4, 2>(vr, vi, lane);
    cnot_v<3, 1>(vr, vi, lane);
    cnot_v<2, 0>(vr, vi, lane);
    mask_xor_L1<0>(vr, vi);
    ctrl_regswap<8>(vr, vi, (((lane >> 1) ^ (lane >> 3)) & 1) != 0);
    ctrl_regswap<4>(vr, vi, ((lane ^ (lane >> 2) ^ (lane >> 4)) & 1) != 0);
}
__device__ __forceinline__ void cnot_layer2_noll(ull* vr, ull* vi, int lane) {
    cnots_seq<2, 2, 6>(vr, vi, lane);
    cnot_trail_j<3, 0>(vr, vi);
}
__device__ __forceinline__ void cnot_layer3_def(ull* vr, ull* vi, int lane) {
    cnot_v<4, 0>(vr, vi, lane);
    mask_xor_L3<0>(vr, vi);
    ctrl_regswap<8>(vr, vi, ((lane >> 3) & 1) != 0);
    ctrl_regswap<4>(vr, vi, ((lane >> 2) & 1) != 0);
    ctrl_regswap<2>(vr, vi, ((lane >> 1) & 1) != 0);
    ctrl_regswap<1>(vr, vi, ((lane ^ (lane >> 4)) & 1) != 0);
}

// ---- domain transpose: R11 float scheme, dual buffers ---------------------
// Per-array scratch: 32 rows x 34 floats (136B stride). Write: row=(2j+h),
// float-col=lane (conflict-free STS.32). Read: row = (remapped) lane,
// cols (tc, tc+1) contiguous -> one LDS.64 per reg; pair-swap if tr_swap.
#define TR_STRIDE 34
__device__ constexpr int tr_col(int mode, int j) {
    if (mode == 1) {
        int c1 = (j & 1) ^ ((j >> 2) & 1);
        int c2 = ((j >> 1) & 1) ^ ((j >> 3) & 1);
        return (c1 << 1) | (c2 << 2) | (((j >> 2) & 1) << 3) | (((j >> 3) & 1) << 4);
    }
    return 2 * j;
}
__device__ constexpr bool tr_swap(int mode, int j) {
    if (mode == 1) return ((j >> 1) & 1) != 0;
    if (mode == 2) return ((j >> 3) & 1) != 0;
    return false;
}
template <int MODE, int J>
__device__ __forceinline__ void tr_read2(ull* vr, ull* vi,
                                         const float* rpr, const float* rpi) {
    if constexpr (J < 16) {
        ull tr = *(const ull*)(rpr + tr_col(MODE, J));
        ull ti = *(const ull*)(rpi + tr_col(MODE, J));
        if constexpr (tr_swap(MODE, J)) { tr = swap64(tr); ti = swap64(ti); }
        vr[J] = tr; vi[J] = ti;
        tr_read2<MODE, J + 1>(vr, vi, rpr, rpi);
    }
}
template <int MODE>
__device__ __forceinline__ void transpose_domains(ull* vr, ull* vi,
                                                  float* scr, float* sci, int lane) {
    float* wr = scr + lane;
    float* wi = sci + lane;
#pragma unroll
    for (int j = 0; j < 16; j++) {
        float f0, f1;
        unpack2(vr[j], f0, f1);
        wr[(2 * j) * TR_STRIDE]     = f0;
        wr[(2 * j + 1) * TR_STRIDE] = f1;
        unpack2(vi[j], f0, f1);
        wi[(2 * j) * TR_STRIDE]     = f0;
        wi[(2 * j + 1) * TR_STRIDE] = f1;
    }
    __syncwarp();
    int R = lane;
    if constexpr (MODE == 1)
        R = lane ^ ((lane >> 3) & 1) ^ ((((lane >> 4) & 1)) << 1);
    tr_read2<MODE, 0>(vr, vi, scr + R * TR_STRIDE, sci + R * TR_STRIDE);
    __syncwarp();
}

// ---- merged diagonal pass --------------------------------------------------
__device__ __forceinline__ void apply_G(ull* vr, ull* vi,
                                        const ulonglong2* __restrict__ sG,
                                        int base) {
#pragma unroll
    for (int j = 0; j < 16; j++) {
        ulonglong2 g = sG[base + j * 32];
        ull GR = g.x, GI = g.y;
        ull NGI = GI ^ SGN2;
        ull nr = fma2(GR, vr[j], mul2(NGI, vi[j]));
        ull ni = fma2(GR, vi[j], mul2(GI, vr[j]));
        vr[j] = nr; vi[j] = ni;
    }
}

// ---- Y layer: reg gates, (folded) transpose, reg gates --------------------
template <int L, int PH, int I>
__device__ __forceinline__ void y_phase(ull* vr, ull* vi,
                                        const float* __restrict__ sY) {
    if constexpr (I < 5) {
        constexpr int q = (PH == 0) ? 5 + I : I;
        y_gate<5 + I>(vr, vi, sY[(L - 1) * 10 + q]);
        y_phase<L, PH, I + 1>(vr, vi, sY);
    }
}
template <int L, int MODE>
__device__ __forceinline__ void y_layer2(ull* vr, ull* vi, int lane,
                                         const float* __restrict__ sY,
                                         float* scr, float* sci) {
    constexpr int p = (L - 1) % 2;
    y_phase<L, p, 0>(vr, vi, sY);
    transpose_domains<MODE>(vr, vi, scr, sci, lane);
    y_phase<L, p ^ 1, 0>(vr, vi, sY);
}

__device__ __forceinline__ float wht5(float v, int lane) {
#pragma unroll
    for (int m = 1; m < 32; m <<= 1) {
        float u = shxf(v, m);
        v = (lane & m) ? (u - v) : (u + v);
    }
    return v;
}

// ---- main kernel ----------------------------------------------------------
__global__ void __launch_bounds__(256, 2)
qsim_kernel(const float* __restrict__ x, const float* __restrict__ Wm,
            const float* __restrict__ b, float* __restrict__ out) {
    extern __shared__ float smem[];
    float* sG4f = smem;                 // 10240 floats
    float* sW   = smem + 10240;         // 640
    float* sY   = smem + 10880;         // 50
    float* sV   = smem + 10930;         // 40
    float* sb   = smem + 10970;         // 16
    float* sTr  = smem + 10988;         // 8 warps x 2176 floats (dual buffers)

    const int tid = threadIdx.x;
    {
        float4* d4 = (float4*)sG4f;
        const float4* s4 = (const float4*)d_G4f;
        for (int i = tid; i < 2560; i += 256) d4[i] = s4[i];
        for (int i = tid; i < NQ * EMB; i += 256) sW[i] = Wm[i];
        if (tid < 50) sY[tid] = d_Yt[tid];
        if (tid < 40) sV[tid] = d_V0[tid];
        if (tid < 16) sb[tid] = (tid < NQ) ? b[tid] : 0.f;
    }
    __syncthreads();

    const int lane = tid & 31;
    const int e = blockIdx.x * 8 + (tid >> 5);
    float* scr = sTr + (tid >> 5) * 2176;
    float* sci = scr + 1088;

    // angles = x[e] @ W.T + b  (half-angles)
    const float xa = x[e * EMB + lane];
    const float xb = x[e * EMB + 32 + lane];
    float halfang[NQ];
#pragma unroll
    for (int w = 0; w < NQ; w++) {
        float p = xa * sW[w * EMB + lane] + xb * sW[w * EMB + 32 + lane];
#pragma unroll
        for (int m = 16; m >= 1; m >>= 1) p += shxf(p, m);
        halfang[w] = 0.5f * (p + sb[w]);
    }

    // per-qubit vectors v_w = RY(th0) RZ(phi0) RX(a) |0>
    float v0r[NQ], v0i[NQ], v1r[NQ], v1i[NQ];
#pragma unroll
    for (int w = 0; w < NQ; w++) {
        float sa, ca; __sincosf(halfang[w], &sa, &ca);
        float cth = sV[w * 4], sth = sV[w * 4 + 1];
        float cph = sV[w * 4 + 2], sph = sV[w * 4 + 3];
        float P = ca * cph, Q = ca * sph, R = sa * cph, T = sa * sph;
        v0r[w] = cth * P - sth * T;
        v0i[w] = sth * R - cth * Q;
        v1r[w] = sth * P + cth * T;
        v1i[w] = -sth * Q - cth * R;
    }

#define PICKR(w, bit) ((bit) ? v1r[w] : v0r[w])
#define PICKI(w, bit) ((bit) ? v1i[w] : v0i[w])
    const int l0 = lane & 1, l1 = (lane >> 1) & 1, l2 = (lane >> 2) & 1,
              l3 = (lane >> 3) & 1, l4 = (lane >> 4) & 1;

    // init with CNOT-layer-0 folded in
    float PL0r, PL0i, PL1r, PL1i;
    {
        const int e2 = l2 ^ l3, e3 = l1 ^ l2, e4 = l0 ^ l1;
        float ar = PICKR(2, e2), ai = PICKI(2, e2);
        float br = PICKR(3, e3), bi = PICKI(3, e3);
        float pr = ar * br - ai * bi, pi = ar * bi + ai * br;
        float cr = PICKR(4, e4), ci = PICKI(4, e4);
        float Pr = pr * cr - pi * ci, Pi = pr * ci + pi * cr;
        const int a0 = l4, c0 = l3 ^ l4;
        float xr = PICKR(0, a0), xi = PICKI(0, a0);
        float yr = PICKR(1, c0), yi = PICKI(1, c0);
        float A0r = xr * yr - xi * yi, A0i = xr * yi + xi * yr;
        xr = PICKR(0, a0 ^ 1); xi = PICKI(0, a0 ^ 1);
        yr = PICKR(1, c0 ^ 1); yi = PICKI(1, c0 ^ 1);
        float A1r = xr * yr - xi * yi, A1i = xr * yi + xi * yr;
        PL0r = Pr * A0r - Pi * A0i; PL0i = Pr * A0i + Pi * A0r;
        PL1r = Pr * A1r - Pi * A1i; PL1i = Pr * A1i + Pi * A1r;
    }

    float rr[16], ri[16];
    rr[0] = PICKR(5, l0);     ri[0] = PICKI(5, l0);
    rr[8] = PICKR(5, l0 ^ 1); ri[8] = PICKI(5, l0 ^ 1);
#pragma unroll
    for (int j3 = 0; j3 < 2; j3++) {
        const int base = j3 * 8;
        float br = rr[base], bi = ri[base];
        const int a1 = 1 ^ j3;
        rr[base + 4] = br * PICKR(6, a1) - bi * PICKI(6, a1);
        ri[base + 4] = br * PICKI(6, a1) + bi * PICKR(6, a1);
        rr[base]     = br * PICKR(6, j3) - bi * PICKI(6, j3);
        ri[base]     = br * PICKI(6, j3) + bi * PICKR(6, j3);
    }
#pragma unroll
    for (int hi2 = 0; hi2 < 4; hi2++) {
        const int base = hi2 * 4;
        const int j2 = hi2 & 1;
        float br = rr[base], bi = ri[base];
        const int a1 = 1 ^ j2;
        rr[base + 2] = br * PICKR(7, a1) - bi * PICKI(7, a1);
        ri[base + 2] = br * PICKI(7, a1) + bi * PICKR(7, a1);
        rr[base]     = br * PICKR(7, j2) - bi * PICKI(7, j2);
        ri[base]     = br * PICKI(7, j2) + bi * PICKR(7, j2);
    }
#pragma unroll
    for (int hi2 = 0; hi2 < 8; hi2++) {
        const int base = hi2 * 2;
        const int j1 = hi2 & 1;
        float br = rr[base], bi = ri[base];
        const int a1 = 1 ^ j1;
        rr[base + 1] = br * PICKR(8, a1) - bi * PICKI(8, a1);
        ri[base + 1] = br * PICKI(8, a1) + bi * PICKR(8, a1);
        rr[base]     = br * PICKR(8, j1) - bi * PICKI(8, j1);
        ri[base]     = br * PICKI(8, j1) + bi * PICKR(8, j1);
    }

    ull vr[16], vi[16];
    {
        const ull PLr = pack2(PL0r, PL1r), PLi = pack2(PL0i, PL1i);
        const ull NPLi = PLi ^ SGN2;
        const ull V9Re = pack2(v0r[9], v1r[9]), V9Ie = pack2(v0i[9], v1i[9]);
        const ull V9Ro = pack2(v1r[9], v0r[9]), V9Io = pack2(v1i[9], v0i[9]);
        const ull Qer = fma2(PLr, V9Re, mul2(NPLi, V9Ie));
        const ull Qei = fma2(PLr, V9Ie, mul2(PLi, V9Re));
        const ull Qor = fma2(PLr, V9Ro, mul2(NPLi, V9Io));
        const ull Qoi = fma2(PLr, V9Io, mul2(PLi, V9Ro));
#pragma unroll
        for (int j = 0; j < 16; j++) {
            const ull AR = splat2(rr[j]), AI = splat2(ri[j]);
            const ull NAI = AI ^ SGN2;
            const ull Qr = (j & 1) ? Qor : Qer;
            const ull Qi = (j & 1) ? Qoi : Qei;
            vr[j] = fma2(AR, Qr, mul2(NAI, Qi));
            vi[j] = fma2(AR, Qi, mul2(AI, Qr));
        }
    }

    const ulonglong2* sG = (const ulonglong2*)sG4f;
    apply_G(vr, vi, sG, 0 * 512 + lane);
    y_layer2<1, 0>(vr, vi, lane, sY, scr, sci);
    cnot_layer1_def(vr, vi, lane);
    apply_G(vr, vi, sG, 1 * 512 + lane);
    y_layer2<2, 1>(vr, vi, lane, sY, scr, sci);
    cnot_layer2_noll(vr, vi, lane);
    apply_G(vr, vi, sG, 2 * 512 + lane);
    y_layer2<3, 0>(vr, vi, lane, sY, scr, sci);
    cnot_layer3_def(vr, vi, lane);
    apply_G(vr, vi, sG, 3 * 512 + lane);
    y_layer2<4, 2>(vr, vi, lane, sY, scr, sci);
    cnot_layer4(vr, vi, lane);
    apply_G(vr, vi, sG, 4 * 512 + lane);
    y_layer2<5, 0>(vr, vi, lane, sY, scr, sci);

    // readout in pre-restore frame
    float A = 0.f, B = 0.f, C = 0.f, D = 0.f, E = 0.f, F = 0.f, G = 0.f, Hc = 0.f;
#pragma unroll
    for (int j = 0; j < 16; j++) {
        ull p2 = fma2(vr[j], vr[j], mul2(vi[j], vi[j]));
        float plo, phi_; unpack2(p2, plo, phi_);
        float s = plo + phi_;
        float d = plo - phi_;
        A += (j & 8) ? -d : d;
        B += (j & 4) ? -s : s;
        C += (((j >> 3) ^ (j >> 1)) & 1) ? -s : s;
        D += (((j >> 2) ^ j) & 1) ? -s : s;
        E += (j & 2) ? -d : d;
        F += (j & 1) ? -s : s;
        G += (j & 8) ? -s : s;
        Hc += (j & 2) ? -s : s;
    }
    A = wht5(A, lane); B = wht5(B, lane); C = wht5(C, lane); D = wht5(D, lane);
    E = wht5(E, lane); F = wht5(F, lane); G = wht5(G, lane); Hc = wht5(Hc, lane);

    float* o = out + e * NQ;
    if (lane == 0)  o[0] = A;
    if (lane == 16) o[1] = B;
    if (lane == 8)  { o[2] = C; o[6] = G; }
    if (lane == 4)  { o[3] = D; o[7] = B; }
    if (lane == 2)  { o[4] = E; o[8] = Hc; }
    if (lane == 17) o[5] = F;
    if (lane == 1)  o[9] = F;
}

extern "C" void kernel_launch(void* const* d_in, const int* in_sizes, int n_in,
                              void* d_out, int out_size) {
    const float* x       = (const float*)d_in[0];
    const float* Wm      = (const float*)d_in[1];
    const float* b       = (const float*)d_in[2];
    const float* weights = (const float*)d_in[3];
    float* out = (float*)d_out;

    const int smem_bytes = (10988 + 8 * 2176) * sizeof(float);
    cudaFuncSetAttribute(qsim_kernel,
                         cudaFuncAttributeMaxDynamicSharedMemorySize, smem_bytes);

    prep_kernel<<<5, 1024>>>(weights);
    qsim_kernel<<<BATCH / 8, 256, smem_bytes>>>(x, Wm, b, out);
}

// round 16
// speedup vs baseline: 1.0306x; 1.0306x over previous
#include <cuda_runtime.h>
#include <cuda_bf16.h>

// 10-qubit state-vector sim, one warp/element, f32x2 packed.
// Position: bits[9:5]=lane, bits[4:1]=j, bit[0]=half.
// CNOT layer 0 folded into the initial product state. Per layer: CNOT
// remnant, merged diagonal G_l, Y layer (reg gates, lane<->reg transpose,
// reg gates). Lane gathers of layers 1/2/3 folded into adjacent transposes;
// G1,G3 stored lane-permuted. Readout in the pre-restore frame.
// Transpose: single-buffer float scheme (STS.32 writes / LDS.64 reads) —
// measured optimum; dual-buffer and LDS.128+SEL variants both regressed
// (L1D-carveout squeeze / ALU swap). Final transpose drops its dead syncs.

#define NQ 10
#define BATCH 16384
#define EMB 64
#define SGN2 0x8000000080000000ULL

typedef unsigned long long ull;

__device__ float d_G4f[5 * 16 * 32 * 4];
__device__ float d_Yt[50];
__device__ float d_V0[40];

__device__ __forceinline__ ull pack2(float lo, float hi) {
    ull r; asm("mov.b64 %0, {%1,%2};" : "=l"(r) : "f"(lo), "f"(hi)); return r;
}
__device__ __forceinline__ void unpack2(ull v, float& lo, float& hi) {
    asm("mov.b64 {%0,%1}, %2;" : "=f"(lo), "=f"(hi) : "l"(v));
}
__device__ __forceinline__ ull splat2(float x) { return pack2(x, x); }
__device__ __forceinline__ ull fma2(ull a, ull b, ull c) {
    ull d; asm("fma.rn.f32x2 %0, %1, %2, %3;" : "=l"(d) : "l"(a), "l"(b), "l"(c)); return d;
}
__device__ __forceinline__ ull mul2(ull a, ull b) {
    ull d; asm("mul.rn.f32x2 %0, %1, %2;" : "=l"(d) : "l"(a), "l"(b)); return d;
}
__device__ __forceinline__ ull swap64(ull v) {
    float lo, hi; unpack2(v, lo, hi); return pack2(hi, lo);
}
__device__ __forceinline__ float shxf(float v, int m) {
    return __shfl_xor_sync(0xffffffffu, v, m);
}

// ---- prep: diagonals (lane-permuted for l=1,3) + coefficients -------------
__global__ void prep_kernel(const float* __restrict__ weights) {
    const int t = threadIdx.x;
    const int l = blockIdx.x;  // 0..4
    if (l == 0) {
        if (t < 50) {
            int ll = t / 10 + 1, w = t % 10;
            d_Yt[t] = tanf(0.5f * weights[ll * 30 + w * 3 + 1]);
        }
        if (t >= 64 && t < 74) {
            int w = t - 64;
            float phi = weights[w * 3 + 0];
            float th  = weights[w * 3 + 1];
            float sth, cth, sph, cph;
            sincosf(0.5f * th, &sth, &cth);
            sincosf(0.5f * phi, &sph, &cph);
            d_V0[w * 4] = cth; d_V0[w * 4 + 1] = sth;
            d_V0[w * 4 + 2] = cph; d_V0[w * 4 + 3] = sph;
        }
    }
    const int k = t;  // 1024 threads
    {
        const int r = l + 1;
        int m = k;
        for (int w = 9; w >= 0; w--) {
            int c = w, tt = (w + r) % 10;
            if ((m >> (9 - c)) & 1) m ^= 1 << (9 - tt);
        }
        float e = 0.f, scale = 1.f;
        for (int w = 0; w < 10; w++) {
            float phi1 = weights[(l + 1) * 30 + w * 3 + 0];
            float om0  = weights[l * 30 + w * 3 + 2];
            e += 0.5f * phi1 * (((k >> (9 - w)) & 1) ? 1.f : -1.f);
            e += 0.5f * om0  * (((m >> (9 - w)) & 1) ? 1.f : -1.f);
            scale *= cosf(0.5f * weights[(l + 1) * 30 + w * 3 + 1]);
        }
        float gi, gr; sincosf(e, &gi, &gr);
        gr *= scale; gi *= scale;
        int pos = (l & 1) ? (((k & 0x1F) << 5) | ((k >> 5) & 0x1F)) : k;
        int ln = pos >> 5;
        const int jj = (pos >> 1) & 15, hh = pos & 1;
        if (l == 1) {   // slot = F1(lane): b0^=b2, b1^=b3, b2^=b4
            int b = ln;
            ln = b ^ ((b >> 2) & 1) ^ ((((b >> 3) & 1)) << 1) ^ ((((b >> 4) & 1)) << 2);
        } else if (l == 3) {  // slot = F3(lane): b0^=b4
            ln = ln ^ ((ln >> 4) & 1);
        }
        const int b4 = ((l * 16 + jj) * 32 + ln) * 4;
        d_G4f[b4 + hh]     = gr;
        d_G4f[b4 + 2 + hh] = gi;
    }
}

// ---- tangent-form RY shear (reg domain only) ------------------------------
template <int W>
__device__ __forceinline__ void y_gate(ull* vr, ull* vi, float t) {
    constexpr int BIT = 9 - W;
    if constexpr (BIT >= 1) {
        constexpr int MJ = 1 << (BIT - 1);
        const ull T = splat2(t), NT = splat2(-t);
#pragma unroll
        for (int j = 0; j < 16; j++) {
            if (!(j & MJ)) {
                const int j1 = j | MJ;
                ull x0r = vr[j], x0i = vi[j], x1r = vr[j1], x1i = vi[j1];
                vr[j]  = fma2(NT, x1r, x0r);
                vi[j]  = fma2(NT, x1i, x0i);
                vr[j1] = fma2(T, x0r, x1r);
                vi[j1] = fma2(T, x0i, x1i);
            }
        }
    } else {
        const ull SP = pack2(-t, t);
#pragma unroll
        for (int j = 0; j < 16; j++) {
            vr[j] = fma2(SP, swap64(vr[j]), vr[j]);
            vi[j] = fma2(SP, swap64(vi[j]), vi[j]);
        }
    }
}

// ---- single CNOT (qubit template) -----------------------------------------
template <int CQ, int TQ>
__device__ __forceinline__ void cnot_p(ull* vr, ull* vi, int lane) {
    constexpr int BC = 9 - CQ, BT = 9 - TQ;
    if constexpr (BC >= 5 && BT >= 1) {
        constexpr int MCL = 1 << (BC - 5), MJ = 1 << (BT - 1);
        const bool ctrl = (lane & MCL) != 0;
#pragma unroll
        for (int j = 0; j < 16; j++) {
            if (!(j & MJ)) {
                const int j1 = j | MJ;
                ull a = vr[j], b = vr[j1];
                vr[j] = ctrl ? b : a; vr[j1] = ctrl ? a : b;
                ull p = vi[j], q = vi[j1];
                vi[j] = ctrl ? q : p; vi[j1] = ctrl ? p : q;
            }
        }
    } else if constexpr (BC >= 5) {
        constexpr int MCL = 1 << (BC - 5);
        const bool ctrl = (lane & MCL) != 0;
#pragma unroll
        for (int j = 0; j < 16; j++) {
            ull rs = swap64(vr[j]), is = swap64(vi[j]);
            vr[j] = ctrl ? rs : vr[j];
            vi[j] = ctrl ? is : vi[j];
        }
    } else if constexpr (BC >= 1 && BT >= 1) {
        constexpr int MJ = 1 << (BC - 1), MT = 1 << (BT - 1);
#pragma unroll
        for (int j = 0; j < 16; j++) {
            if ((j & MJ) && !(j & MT)) {
                const int j1 = j | MT;
                ull t;
                t = vr[j]; vr[j] = vr[j1]; vr[j1] = t;
                t = vi[j]; vi[j] = vi[j1]; vi[j1] = t;
            }
        }
    } else if constexpr (BC >= 1) {
        constexpr int MJ = 1 << (BC - 1);
#pragma unroll
        for (int j = 0; j < 16; j++) {
            if (j & MJ) { vr[j] = swap64(vr[j]); vi[j] = swap64(vi[j]); }
        }
    }
}
template <int VC, int VT>
__device__ __forceinline__ void cnot_v(ull* vr, ull* vi, int lane) {
    cnot_p<9 - VC, 9 - VT>(vr, vi, lane);
}

template <int MJ>
__device__ __forceinline__ void ctrl_regswap(ull* vr, ull* vi, bool ctrl) {
#pragma unroll
    for (int j = 0; j < 16; j++) {
        if (!(j & MJ)) {
            const int j1 = j | MJ;
            ull a = vr[j], b = vr[j1];
            vr[j] = ctrl ? b : a; vr[j1] = ctrl ? a : b;
            ull p = vi[j], q = vi[j1];
            vi[j] = ctrl ? q : p; vi[j1] = ctrl ? p : q;
        }
    }
}

// ---- Lambda0 merged pieces ------------------------------------------------
__device__ constexpr int trail_mask_ct(int R, int j, int h) {
    int m = 0;
    for (int w = 5; w <= 9; w++) {
        int t = (w + R) % 10;
        if (w + R >= 10 && t <= 4) {
            int bit = (w == 9) ? h : ((j >> (8 - w)) & 1);
            if (bit) m ^= 16 >> t;
        }
    }
    return m;
}
template <int R, int J>
__device__ __forceinline__ void cnot_trail_j(ull* vr, ull* vi) {
    if constexpr (J < 16) {
        constexpr int mlo = trail_mask_ct(R, J, 0);
        constexpr int mhi = trail_mask_ct(R, J, 1);
        if constexpr (mlo != 0 || mhi != 0) {
            float rlo, rhi, ilo, ihi;
            unpack2(vr[J], rlo, rhi);
            unpack2(vi[J], ilo, ihi);
            if constexpr (mlo != 0) { rlo = shxf(rlo, mlo); ilo = shxf(ilo, mlo); }
            if constexpr (mhi != 0) { rhi = shxf(rhi, mhi); ihi = shxf(ihi, mhi); }
            vr[J] = pack2(rlo, rhi);
            vi[J] = pack2(ilo, ihi);
        }
        cnot_trail_j<R, J + 1>(vr, vi);
    }
}
template <int L, int W, int WEND>
__device__ __forceinline__ void cnots_seq(ull* vr, ull* vi, int lane) {
    if constexpr (W <= WEND) {
        cnot_p<W, (W + L % 9 + 1) % 10>(vr, vi, lane);
        cnots_seq<L, W + 1, WEND>(vr, vi, lane);
    }
}
__device__ __forceinline__ void cnot_layer4(ull* vr, ull* vi, int lane) {
    cnots_seq<4, 0, 4>(vr, vi, lane);
    cnot_trail_j<5, 0>(vr, vi);
}

// ---- Lambda1 mask groups (layers 1, 3) ------------------------------------
template <int J>
__device__ __forceinline__ void mask_xor_L1(ull* vr, ull* vi) {
    if constexpr (J < 16) {
        constexpr int mlo = (J & 1) << 4;
        constexpr int mhi = ((J & 1) << 4) | 8;
        float rlo, rhi, ilo, ihi;
        unpack2(vr[J], rlo, rhi);
        unpack2(vi[J], ilo, ihi);
        if constexpr (mlo != 0) { rlo = shxf(rlo, mlo); ilo = shxf(ilo, mlo); }
        rhi = shxf(rhi, mhi); ihi = shxf(ihi, mhi);
        vr[J] = pack2(rlo, rhi);
        vi[J] = pack2(ilo, ihi);
        mask_xor_L1<J + 1>(vr, vi);
    }
}
template <int J>
__device__ __forceinline__ void mask_xor_L3(ull* vr, ull* vi) {
    if constexpr (J < 16) {
        constexpr int base = (((J >> 2) & 1) << 4) | (((J >> 1) & 1) << 3) | ((J & 1) << 2);
        constexpr int mlo = base;
        constexpr int mhi = base | 2;
        float rlo, rhi, ilo, ihi;
        unpack2(vr[J], rlo, rhi);
        unpack2(vi[J], ilo, ihi);
        if constexpr (mlo != 0) { rlo = shxf(rlo, mlo); ilo = shxf(ilo, mlo); }
        rhi = shxf(rhi, mhi); ihi = shxf(ihi, mhi);
        vr[J] = pack2(rlo, rhi);
        vi[J] = pack2(ilo, ihi);
        mask_xor_L3<J + 1>(vr, vi);
    }
}

// ---- CNOT layers with gathers deferred/advanced ---------------------------
__device__ __forceinline__ void cnot_layer1_def(ull* vr, ull* vi, int lane) {
    cnot_v<4, 2>(vr, vi, lane);
    cnot_v<3, 1>(vr, vi, lane);
    cnot_v<2, 0>(vr, vi, lane);
    mask_xor_L1<0>(vr, vi);
    ctrl_regswap<8>(vr, vi, (((lane >> 1) ^ (lane >> 3)) & 1) != 0);
    ctrl_regswap<4>(vr, vi, ((lane ^ (lane >> 2) ^ (lane >> 4)) & 1) != 0);
}
__device__ __forceinline__ void cnot_layer2_noll(ull* vr, ull* vi, int lane) {
    cnots_seq<2, 2, 6>(vr, vi, lane);
    cnot_trail_j<3, 0>(vr, vi);
}
__device__ __forceinline__ void cnot_layer3_def(ull* vr, ull* vi, int lane) {
    cnot_v<4, 0>(vr, vi, lane);
    mask_xor_L3<0>(vr, vi);
    ctrl_regswap<8>(vr, vi, ((lane >> 3) & 1) != 0);
    ctrl_regswap<4>(vr, vi, ((lane >> 2) & 1) != 0);
    ctrl_regswap<2>(vr, vi, ((lane >> 1) & 1) != 0);
    ctrl_regswap<1>(vr, vi, ((lane ^ (lane >> 4)) & 1) != 0);
}

// ---- domain transpose via smem (champion single-buffer scheme) ------------
#define TR_STRIDE 34
__device__ constexpr int tr_col(int mode, int j) {
    if (mode == 1) {
        int c1 = (j & 1) ^ ((j >> 2) & 1);
        int c2 = ((j >> 1) & 1) ^ ((j >> 3) & 1);
        return (c1 << 1) | (c2 << 2) | (((j >> 2) & 1) << 3) | (((j >> 3) & 1) << 4);
    }
    return 2 * j;
}
__device__ constexpr bool tr_swap(int mode, int j) {
    if (mode == 1) return ((j >> 1) & 1) != 0;
    if (mode == 2) return ((j >> 3) & 1) != 0;
    return false;
}
template <int MODE, int J>
__device__ __forceinline__ void tr_read(ull* v, const float* rp) {
    if constexpr (J < 16) {
        ull t = *(const ull*)(rp + tr_col(MODE, J));
        if constexpr (tr_swap(MODE, J)) t = swap64(t);
        v[J] = t;
        tr_read<MODE, J + 1>(v, rp);
    }
}
template <int MODE, bool LAST>
__device__ __forceinline__ void transpose_arr(ull* v, float* sc, int lane) {
    float* wp = sc + lane;
#pragma unroll
    for (int j = 0; j < 16; j++) {
        float f0, f1; unpack2(v[j], f0, f1);
        wp[(2 * j) * TR_STRIDE]     = f0;
        wp[(2 * j + 1) * TR_STRIDE] = f1;
    }
    __syncwarp();
    int row = lane;
    if constexpr (MODE == 1)
        row = lane ^ ((lane >> 3) & 1) ^ ((((lane >> 4) & 1)) << 1);
    tr_read<MODE, 0>(v, sc + row * TR_STRIDE);
    if constexpr (!LAST) __syncwarp();
}
template <int MODE, bool FINAL = false>
__device__ __forceinline__ void transpose_domains(ull* vr, ull* vi, float* sc, int lane) {
    transpose_arr<MODE, false>(vr, sc, lane);
    transpose_arr<MODE, FINAL>(vi, sc, lane);
}

// ---- merged diagonal pass --------------------------------------------------
__device__ __forceinline__ void apply_G(ull* vr, ull* vi,
                                        const ulonglong2* __restrict__ sG,
                                        int base) {
#pragma unroll
    for (int j = 0; j < 16; j++) {
        ulonglong2 g = sG[base + j * 32];
        ull GR = g.x, GI = g.y;
        ull NGI = GI ^ SGN2;
        ull nr = fma2(GR, vr[j], mul2(NGI, vi[j]));
        ull ni = fma2(GR, vi[j], mul2(GI, vr[j]));
        vr[j] = nr; vi[j] = ni;
    }
}

// ---- Y layer: reg gates, (folded) transpose, reg gates --------------------
template <int L, int PH, int I>
__device__ __forceinline__ void y_phase(ull* vr, ull* vi,
                                        const float* __restrict__ sY) {
    if constexpr (I < 5) {
        constexpr int q = (PH == 0) ? 5 + I : I;
        y_gate<5 + I>(vr, vi, sY[(L - 1) * 10 + q]);
        y_phase<L, PH, I + 1>(vr, vi, sY);
    }
}
template <int L, int MODE, bool FINAL = false>
__device__ __forceinline__ void y_layer2(ull* vr, ull* vi, int lane,
                                         const float* __restrict__ sY,
                                         float* sc) {
    constexpr int p = (L - 1) % 2;
    y_phase<L, p, 0>(vr, vi, sY);
    transpose_domains<MODE, FINAL>(vr, vi, sc, lane);
    y_phase<L, p ^ 1, 0>(vr, vi, sY);
}

__device__ __forceinline__ float wht5(float v, int lane) {
#pragma unroll
    for (int m = 1; m < 32; m <<= 1) {
        float u = shxf(v, m);
        v = (lane & m) ? (u - v) : (u + v);
    }
    return v;
}

// ---- main kernel ----------------------------------------------------------
__global__ void __launch_bounds__(256, 2)
qsim_kernel(const float* __restrict__ x, const float* __restrict__ Wm,
            const float* __restrict__ b, float* __restrict__ out) {
    extern __shared__ float smem[];
    float* sG4f = smem;                 // 10240 floats
    float* sW   = smem + 10240;         // 640
    float* sY   = smem + 10880;         // 50
    float* sV   = smem + 10930;         // 40
    float* sb   = smem + 10970;         // 16
    float* sTr  = smem + 10988;         // 8 warps x 1088 floats

    const int tid = threadIdx.x;
    {
        float4* d4 = (float4*)sG4f;
        const float4* s4 = (const float4*)d_G4f;
        for (int i = tid; i < 2560; i += 256) d4[i] = s4[i];
        for (int i = tid; i < NQ * EMB; i += 256) sW[i] = Wm[i];
        if (tid < 50) sY[tid] = d_Yt[tid];
        if (tid < 40) sV[tid] = d_V0[tid];
        if (tid < 16) sb[tid] = (tid < NQ) ? b[tid] : 0.f;
    }
    __syncthreads();

    const int lane = tid & 31;
    const int e = blockIdx.x * 8 + (tid >> 5);
    float* sc = sTr + (tid >> 5) * (32 * TR_STRIDE);

    // angles = x[e] @ W.T + b  (half-angles)
    const float xa = __ldg(&x[e * EMB + lane]);
    const float xb = __ldg(&x[e * EMB + 32 + lane]);
    float halfang[NQ];
#pragma unroll
    for (int w = 0; w < NQ; w++) {
        float p = xa * sW[w * EMB + lane] + xb * sW[w * EMB + 32 + lane];
#pragma unroll
        for (int m = 16; m >= 1; m >>= 1) p += shxf(p, m);
        halfang[w] = 0.5f * (p + sb[w]);
    }

    // per-qubit vectors v_w = RY(th0) RZ(phi0) RX(a) |0>
    float v0r[NQ], v0i[NQ], v1r[NQ], v1i[NQ];
#pragma unroll
    for (int w = 0; w < NQ; w++) {
        float sa, ca; __sincosf(halfang[w], &sa, &ca);
        float cth = sV[w * 4], sth = sV[w * 4 + 1];
        float cph = sV[w * 4 + 2], sph = sV[w * 4 + 3];
        float P = ca * cph, Q = ca * sph, R = sa * cph, T = sa * sph;
        v0r[w] = cth * P - sth * T;
        v0i[w] = sth * R - cth * Q;
        v1r[w] = sth * P + cth * T;
        v1i[w] = -sth * Q - cth * R;
    }

#define PICKR(w, bit) ((bit) ? v1r[w] : v0r[w])
#define PICKI(w, bit) ((bit) ? v1i[w] : v0i[w])
    const int l0 = lane & 1, l1 = (lane >> 1) & 1, l2 = (lane >> 2) & 1,
              l3 = (lane >> 3) & 1, l4 = (lane >> 4) & 1;

    // init with CNOT-layer-0 folded in
    float PL0r, PL0i, PL1r, PL1i;
    {
        const int e2 = l2 ^ l3, e3 = l1 ^ l2, e4 = l0 ^ l1;
        float ar = PICKR(2, e2), ai = PICKI(2, e2);
        float br = PICKR(3, e3), bi = PICKI(3, e3);
        float pr = ar * br - ai * bi, pi = ar * bi + ai * br;
        float cr = PICKR(4, e4), ci = PICKI(4, e4);
        float Pr = pr * cr - pi * ci, Pi = pr * ci + pi * cr;
        const int a0 = l4, c0 = l3 ^ l4;
        float xr = PICKR(0, a0), xi = PICKI(0, a0);
        float yr = PICKR(1, c0), yi = PICKI(1, c0);
        float A0r = xr * yr - xi * yi, A0i = xr * yi + xi * yr;
        xr = PICKR(0, a0 ^ 1); xi = PICKI(0, a0 ^ 1);
        yr = PICKR(1, c0 ^ 1); yi = PICKI(1, c0 ^ 1);
        float A1r = xr * yr - xi * yi, A1i = xr * yi + xi * yr;
        PL0r = Pr * A0r - Pi * A0i; PL0i = Pr * A0i + Pi * A0r;
        PL1r = Pr * A1r - Pi * A1i; PL1i = Pr * A1i + Pi * A1r;
    }

    float rr[16], ri[16];
    rr[0] = PICKR(5, l0);     ri[0] = PICKI(5, l0);
    rr[8] = PICKR(5, l0 ^ 1); ri[8] = PICKI(5, l0 ^ 1);
#pragma unroll
    for (int j3 = 0; j3 < 2; j3++) {
        const int base = j3 * 8;
        float br = rr[base], bi = ri[base];
        const int a1 = 1 ^ j3;
        rr[base + 4] = br * PICKR(6, a1) - bi * PICKI(6, a1);
        ri[base + 4] = br * PICKI(6, a1) + bi * PICKR(6, a1);
        rr[base]     = br * PICKR(6, j3) - bi * PICKI(6, j3);
        ri[base]     = br * PICKI(6, j3) + bi * PICKR(6, j3);
    }
#pragma unroll
    for (int hi2 = 0; hi2 < 4; hi2++) {
        const int base = hi2 * 4;
        const int j2 = hi2 & 1;
        float br = rr[base], bi = ri[base];
        const int a1 = 1 ^ j2;
        rr[base + 2] = br * PICKR(7, a1) - bi * PICKI(7, a1);
        ri[base + 2] = br * PICKI(7, a1) + bi * PICKR(7, a1);
        rr[base]     = br * PICKR(7, j2) - bi * PICKI(7, j2);
        ri[base]     = br * PICKI(7, j2) + bi * PICKR(7, j2);
    }
#pragma unroll
    for (int hi2 = 0; hi2 < 8; hi2++) {
        const int base = hi2 * 2;
        const int j1 = hi2 & 1;
        float br = rr[base], bi = ri[base];
        const int a1 = 1 ^ j1;
        rr[base + 1] = br * PICKR(8, a1) - bi * PICKI(8, a1);
        ri[base + 1] = br * PICKI(8, a1) + bi * PICKR(8, a1);
        rr[base]     = br * PICKR(8, j1) - bi * PICKI(8, j1);
        ri[base]     = br * PICKI(8, j1) + bi * PICKR(8, j1);
    }

    ull vr[16], vi[16];
    {
        const ull PLr = pack2(PL0r, PL1r), PLi = pack2(PL0i, PL1i);
        const ull NPLi = PLi ^ SGN2;
        const ull V9Re = pack2(v0r[9], v1r[9]), V9Ie = pack2(v0i[9], v1i[9]);
        const ull V9Ro = pack2(v1r[9], v0r[9]), V9Io = pack2(v1i[9], v0i[9]);
        const ull Qer = fma2(PLr, V9Re, mul2(NPLi, V9Ie));
        const ull Qei = fma2(PLr, V9Ie, mul2(PLi, V9Re));
        const ull Qor = fma2(PLr, V9Ro, mul2(NPLi, V9Io));
        const ull Qoi = fma2(PLr, V9Io, mul2(PLi, V9Ro));
#pragma unroll
        for (int j = 0; j < 16; j++) {
            const ull AR = splat2(rr[j]), AI = splat2(ri[j]);
            const ull NAI = AI ^ SGN2;
            const ull Qr = (j & 1) ? Qor : Qer;
            const ull Qi = (j & 1) ? Qoi : Qei;
            vr[j] = fma2(AR, Qr, mul2(NAI, Qi));
            vi[j] = fma2(AR, Qi, mul2(AI, Qr));
        }
    }

    const ulonglong2* sG = (const ulonglong2*)sG4f;
    apply_G(vr, vi, sG, 0 * 512 + lane);
    y_layer2<1, 0>(vr, vi, lane, sY, sc);
    cnot_layer1_def(vr, vi, lane);
    apply_G(vr, vi, sG, 1 * 512 + lane);
    y_layer2<2, 1>(vr, vi, lane, sY, sc);
    cnot_layer2_noll(vr, vi, lane);
    apply_G(vr, vi, sG, 2 * 512 + lane);
    y_layer2<3, 0>(vr, vi, lane, sY, sc);
    cnot_layer3_def(vr, vi, lane);
    apply_G(vr, vi, sG, 3 * 512 + lane);
    y_layer2<4, 2>(vr, vi, lane, sY, sc);
    cnot_layer4(vr, vi, lane);
    apply_G(vr, vi, sG, 4 * 512 + lane);
    y_layer2<5, 0, true>(vr, vi, lane, sY, sc);   // final: drop dead trailing sync

    // readout in pre-restore frame
    float A = 0.f, B = 0.f, C = 0.f, D = 0.f, E = 0.f, F = 0.f, G = 0.f, Hc = 0.f;
#pragma unroll
    for (int j = 0; j < 16; j++) {
        ull p2 = fma2(vr[j], vr[j], mul2(vi[j], vi[j]));
        float plo, phi_; unpack2(p2, plo, phi_);
        float s = plo + phi_;
        float d = plo - phi_;
        A += (j & 8) ? -d : d;
        B += (j & 4) ? -s : s;
        C += (((j >> 3) ^ (j >> 1)) & 1) ? -s : s;
        D += (((j >> 2) ^ j) & 1) ? -s : s;
        E += (j & 2) ? -d : d;
        F += (j & 1) ? -s : s;
        G += (j & 8) ? -s : s;
        Hc += (j & 2) ? -s : s;
    }
    A = wht5(A, lane); B = wht5(B, lane); C = wht5(C, lane); D = wht5(D, lane);
    E = wht5(E, lane); F = wht5(F, lane); G = wht5(G, lane); Hc = wht5(Hc, lane);

    float* o = out + e * NQ;
    if (lane == 0)  o[0] = A;
    if (lane == 16) o[1] = B;
    if (lane == 8)  { o[2] = C; o[6] = G; }
    if (lane == 4)  { o[3] = D; o[7] = B; }
    if (lane == 2)  { o[4] = E; o[8] = Hc; }
    if (lane == 17) o[5] = F;
    if (lane == 1)  o[9] = F;
}

extern "C" void kernel_launch(void* const* d_in, const int* in_sizes, int n_in,
                              void* d_out, int out_size) {
    const float* x       = (const float*)d_in[0];
    const float* Wm      = (const float*)d_in[1];
    const float* b       = (const float*)d_in[2];
    const float* weights = (const float*)d_in[3];
    float* out = (float*)d_out;

    const int smem_bytes = (10988 + 8 * 32 * TR_STRIDE) * sizeof(float);
    cudaFuncSetAttribute(qsim_kernel,
                         cudaFuncAttributeMaxDynamicSharedMemorySize, smem_bytes);

    prep_kernel<<<5, 1024>>>(weights);
    qsim_kernel<<<BATCH / 8, 256, smem_bytes>>>(x, Wm, b, out);
}